// round 14
// baseline (speedup 1.0000x reference)
#include <cuda_runtime.h>
#include <cuda_bf16.h>
#include <cstdint>
#include <math_constants.h>

// ---------------------------------------------------------------------------
// Problem constants
// ---------------------------------------------------------------------------
#define NROWS  32768        // 8 * 4096 query rows
#define KCODES 8192
#define DIM    256          // GEMM-K
#define MT     128          // rows per CTA
#define NTILE  128          // codes per N-tile
#define NTILES (KCODES / NTILE)     // 64

#define NTHREADS 256

// SMEM layout (bytes) -- 104960 total => two CTAs per SM (209920 <= 228KB)
#define ROWA        528     // 256 bf16 + 8 pad (conflict-free ldmatrix)
#define SM_B        67584   // 2 k64-stage buffers after A (128*528)
#define STAGE_BYTES 18432   // 128 codes * 144B
#define ROWB        144     // 128B k64 slice + 16 pad
#define SM_CSQ      104448  // 512B csq tile
#define SMEM_TOTAL  104960

// ---------------------------------------------------------------------------
// Device scratch (no allocations allowed)
// ---------------------------------------------------------------------------
__device__ uint4 g_cb_hi4[KCODES * DIM / 8];   // bf16 hi, 512B per code row
__device__ __align__(16) float g_csq[KCODES];
__device__ int g_cand[NROWS * 8];              // top-2 per warp-column x 4

// ---------------------------------------------------------------------------
// PTX helpers (base ISA only: ldmatrix / mma.sync / cp.async)
// ---------------------------------------------------------------------------
__device__ __forceinline__ uint32_t smem_to_u32(const void* smem_ptr) {
    uint32_t addr;
    asm("{ .reg .u64 tmp; cvta.to.shared.u64 tmp, %1; cvt.u32.u64 %0, tmp; }"
        : "=r"(addr) : "l"(smem_ptr));
    return addr;
}

#define CP_ASYNC16(dst, src) \
    asm volatile("cp.async.cg.shared.global [%0], [%1], 16;" \
        :: "r"((uint32_t)(dst)), "l"((const void*)(src)) : "memory")
#define CP_COMMIT() asm volatile("cp.async.commit_group;" ::: "memory")
#define CP_WAIT(n)  asm volatile("cp.async.wait_group %0;" :: "n"(n) : "memory")

#define LDSM_X4(r, addr) \
    asm volatile("ldmatrix.sync.aligned.m8n8.x4.shared.b16 {%0,%1,%2,%3}, [%4];" \
        : "=r"((r)[0]), "=r"((r)[1]), "=r"((r)[2]), "=r"((r)[3]) : "r"(addr))
#define LDSM_X2(r, addr) \
    asm volatile("ldmatrix.sync.aligned.m8n8.x2.shared.b16 {%0,%1}, [%2];" \
        : "=r"((r)[0]), "=r"((r)[1]) : "r"(addr))

#define MMA_BF16(c, a, b) \
    asm volatile("mma.sync.aligned.m16n8k16.row.col.f32.bf16.bf16.f32 " \
        "{%0,%1,%2,%3}, {%4,%5,%6,%7}, {%8,%9}, {%0,%1,%2,%3};" \
        : "+f"((c)[0]), "+f"((c)[1]), "+f"((c)[2]), "+f"((c)[3]) \
        : "r"((a)[0]), "r"((a)[1]), "r"((a)[2]), "r"((a)[3]), \
          "r"((b)[0]), "r"((b)[1]))

// merge candidate (C1,J1) then (C2,J2) into running top-2 (B1,I1,B2,I2)
#define MERGE2(B1, I1, B2, I2, C1, J1, C2, J2) do { \
    if ((C1) < (B1)) { \
        float _nb2; int _ni2; \
        if ((B1) < (C2)) { _nb2 = (B1); _ni2 = (I1); } \
        else             { _nb2 = (C2); _ni2 = (J2); } \
        (B1) = (C1); (I1) = (J1); (B2) = _nb2; (I2) = _ni2; \
    } else if ((C1) < (B2)) { (B2) = (C1); (I2) = (J1); } \
} while (0)

// ---------------------------------------------------------------------------
// Codebook prep: one warp per code row. bf16 hi + fp32 csq.
// ---------------------------------------------------------------------------
__global__ __launch_bounds__(256) void vq_prep(const float* __restrict__ cb) {
    int row  = blockIdx.x * 8 + (threadIdx.x >> 5);
    int lane = threadIdx.x & 31;
    const float4* cr = (const float4*)(cb + (size_t)row * DIM);
    float sq = 0.f;
    uint32_t hw[4];
#pragma unroll
    for (int q = 0; q < 2; q++) {
        float4 v = cr[lane * 2 + q];
        sq += v.x * v.x + v.y * v.y + v.z * v.z + v.w * v.w;
        __nv_bfloat162 p0; p0.x = __float2bfloat16_rn(v.x); p0.y = __float2bfloat16_rn(v.y);
        __nv_bfloat162 p1; p1.x = __float2bfloat16_rn(v.z); p1.y = __float2bfloat16_rn(v.w);
        hw[q * 2 + 0] = *reinterpret_cast<uint32_t*>(&p0);
        hw[q * 2 + 1] = *reinterpret_cast<uint32_t*>(&p1);
    }
    g_cb_hi4[row * 32 + lane] = make_uint4(hw[0], hw[1], hw[2], hw[3]);
#pragma unroll
    for (int off = 16; off; off >>= 1) sq += __shfl_xor_sync(0xffffffffu, sq, off);
    if (lane == 0) g_csq[row] = sq;
}

// ---------------------------------------------------------------------------
// B stage loader: 128 codes x 64 bf16 (one k64 slice) into padded smem rows.
// ---------------------------------------------------------------------------
__device__ __forceinline__ void load_b_stage(uint32_t sbase, int buf, int ktile,
                                             int s, int tid) {
    const char* src = (const char*)g_cb_hi4 + (size_t)ktile * NTILE * 512 + s * 128;
    uint32_t dst = sbase + SM_B + (uint32_t)buf * STAGE_BYTES;
#pragma unroll
    for (int u = tid; u < 1024; u += NTHREADS) {
        int n = u >> 3, j = u & 7;
        CP_ASYNC16(dst + n * ROWB + j * 16, src + (size_t)n * 512 + j * 16);
    }
}

// ---------------------------------------------------------------------------
// Main kernel: grid 256, OCCUPANCY 2. 8 warps of 64x32 tiles, 1-pass bf16,
// 2-buffer k64 staging. Crossbar load ~224 B/MMA (vs 352 at R13).
// ---------------------------------------------------------------------------
__global__ __launch_bounds__(NTHREADS, 2) void vq_main(const float* __restrict__ x) {
    extern __shared__ char smem[];
    const uint32_t sbase = smem_to_u32(smem);
    const int tid  = threadIdx.x;
    const int lane = tid & 31;
    const int wm = (tid >> 5) >> 2;          // 0..1 : 64-row band
    const int wn = (tid >> 5) & 3;           // 0..3 : 32-col band
    const int rowBase = blockIdx.x * MT;

    // ---- A -> bf16 in smem (row stride 528B) ----
    {
        int r = tid >> 1, h = tid & 1;
        const float4* xr = (const float4*)(x + (size_t)(rowBase + r) * DIM + h * 128);
        uint32_t* ah = (uint32_t*)(smem + r * ROWA + h * 256);
#pragma unroll
        for (int q = 0; q < 32; q++) {
            float4 v = xr[q];
            __nv_bfloat162 p0; p0.x = __float2bfloat16_rn(v.x); p0.y = __float2bfloat16_rn(v.y);
            __nv_bfloat162 p1; p1.x = __float2bfloat16_rn(v.z); p1.y = __float2bfloat16_rn(v.w);
            ah[q * 2 + 0] = *reinterpret_cast<uint32_t*>(&p0);
            ah[q * 2 + 1] = *reinterpret_cast<uint32_t*>(&p1);
        }
    }

    // per-lane ldmatrix base addresses
    const uint32_t aBase = sbase + (uint32_t)((wm * 64 + (lane & 15)) * ROWA
                                              + ((lane >> 4) & 1) * 16);
    const uint32_t bLane = (uint32_t)((wn * 32 + (lane & 7)) * ROWB
                                      + ((lane >> 3) & 1) * 16);

    float b1r[8], b2r[8];
    int   i1r[8], i2r[8];
#pragma unroll
    for (int s = 0; s < 8; s++) {
        b1r[s] = CUDART_INF_F; b2r[s] = CUDART_INF_F; i1r[s] = 0; i2r[s] = 1;
    }

    for (int ktile = 0; ktile < NTILES; ktile++) {
        __syncthreads();    // A ready (first iter) / prev epilogue done with csq+B
        load_b_stage(sbase, 0, ktile, 0, tid);
        if (tid < 32) {
            CP_ASYNC16(sbase + SM_CSQ + tid * 16,
                       (const char*)g_csq + (size_t)ktile * 512 + tid * 16);
        }
        CP_COMMIT();

        float c[4][4][4];
#pragma unroll
        for (int a = 0; a < 4; a++)
#pragma unroll
            for (int b = 0; b < 4; b++)
#pragma unroll
                for (int v = 0; v < 4; v++) c[a][b][v] = 0.f;

        for (int s = 0; s < 4; s++) {
            if (s < 3) {
                load_b_stage(sbase, (s + 1) & 1, ktile, s + 1, tid);
                CP_COMMIT();
                CP_WAIT(1);
            } else {
                CP_WAIT(0);
            }
            __syncthreads();
            const uint32_t bufB = sbase + SM_B + ((s & 1) ? STAGE_BYTES : 0);
#pragma unroll
            for (int kk = 0; kk < 4; kk++) {
                const int kg = s * 64 + kk * 16;
                uint32_t ah[4][4], bh[4][2];
#pragma unroll
                for (int mt = 0; mt < 4; mt++)
                    LDSM_X4(ah[mt], aBase + mt * (16 * ROWA) + kg * 2);
#pragma unroll
                for (int nt = 0; nt < 4; nt++)
                    LDSM_X2(bh[nt], bufB + bLane + nt * (8 * ROWB) + kk * 32);
#pragma unroll
                for (int mt = 0; mt < 4; mt++)
#pragma unroll
                    for (int nt = 0; nt < 4; nt++)
                        MMA_BF16(c[mt][nt], ah[mt], bh[nt]);
            }
            __syncthreads();   // compute done before next stage overwrites buf
        }

        // ---- epilogue: scores + running top-2 with skip test ----
        const float* csq_s = (const float*)(smem + SM_CSQ);
        float csqr[8];
#pragma unroll
        for (int nt = 0; nt < 4; nt++) {
            csqr[nt * 2 + 0] = csq_s[wn * 32 + nt * 8 + (lane & 3) * 2 + 0];
            csqr[nt * 2 + 1] = csq_s[wn * 32 + nt * 8 + (lane & 3) * 2 + 1];
        }
        const int kb = ktile * NTILE + wn * 32 + (lane & 3) * 2;
#pragma unroll
        for (int slot = 0; slot < 8; slot++) {
            const int mt = slot >> 1, h = slot & 1;
            float m = CUDART_INF_F;
#pragma unroll
            for (int nt = 0; nt < 4; nt++) {
                m = fminf(m, fmaf(-2.f, c[mt][nt][h * 2 + 0], csqr[nt * 2 + 0]));
                m = fminf(m, fmaf(-2.f, c[mt][nt][h * 2 + 1], csqr[nt * 2 + 1]));
            }
            if (m < b2r[slot]) {
#pragma unroll
                for (int nt = 0; nt < 4; nt++)
#pragma unroll
                    for (int u = 0; u < 2; u++) {
                        float sc = fmaf(-2.f, c[mt][nt][h * 2 + u], csqr[nt * 2 + u]);
                        int k = kb + nt * 8 + u;
                        if (sc < b1r[slot]) {
                            b2r[slot] = b1r[slot]; i2r[slot] = i1r[slot];
                            b1r[slot] = sc;        i1r[slot] = k;
                        } else if (sc < b2r[slot]) {
                            b2r[slot] = sc; i2r[slot] = k;
                        }
                    }
            }
        }
    }

    // ---- lane-quad merge (lanes sharing a row differ in lane&3) ----
#pragma unroll
    for (int slot = 0; slot < 8; slot++) {
        float B1 = b1r[slot], B2 = b2r[slot];
        int   I1 = i1r[slot], I2 = i2r[slot];
#pragma unroll
        for (int off = 1; off <= 2; off <<= 1) {
            float C1 = __shfl_xor_sync(0xffffffffu, B1, off);
            int   J1 = __shfl_xor_sync(0xffffffffu, I1, off);
            float C2 = __shfl_xor_sync(0xffffffffu, B2, off);
            int   J2 = __shfl_xor_sync(0xffffffffu, I2, off);
            MERGE2(B1, I1, B2, I2, C1, J1, C2, J2);
        }
        b1r[slot] = B1; i1r[slot] = I1; b2r[slot] = B2; i2r[slot] = I2;
    }

    // ---- write per-warp-column top-2 (8 candidates per row) ----
    __syncthreads();
    int* mi1 = (int*)(smem + SM_B);
    int* mi2 = (int*)(smem + SM_B + 2048);
    if ((lane & 3) == 0) {
#pragma unroll
        for (int slot = 0; slot < 8; slot++) {
            int row = wm * 64 + (slot >> 1) * 16 + (slot & 1) * 8 + (lane >> 2);
            int idx = wn * 128 + row;
            mi1[idx] = i1r[slot]; mi2[idx] = i2r[slot];
        }
    }
    __syncthreads();
    if (tid < 128) {
#pragma unroll
        for (int w = 0; w < 4; w++) {
            g_cand[(rowBase + tid) * 8 + w * 2 + 0] = mi1[w * 128 + tid];
            g_cand[(rowBase + tid) * 8 + w * 2 + 1] = mi2[w * 128 + tid];
        }
    }
}

// ---------------------------------------------------------------------------
// Exact fp32 rescore of 8 candidates + gather. One warp per row.
// ---------------------------------------------------------------------------
__global__ __launch_bounds__(256) void vq_rescore(const float* __restrict__ x,
                                                  const float* __restrict__ cb,
                                                  float* __restrict__ out) {
    int row  = blockIdx.x * 8 + (threadIdx.x >> 5);
    int lane = threadIdx.x & 31;
    int kc[8];
#pragma unroll
    for (int c = 0; c < 8; c++) kc[c] = g_cand[row * 8 + c];
    const float4* xr = (const float4*)(x + (size_t)row * DIM);
    float4 xv0 = xr[lane], xv1 = xr[lane + 32];
    float d[8];
#pragma unroll
    for (int c = 0; c < 8; c++) {
        const float4* cc = (const float4*)(cb + (size_t)kc[c] * DIM);
        float4 a = cc[lane], b = cc[lane + 32];
        d[c] = xv0.x * a.x + xv0.y * a.y + xv0.z * a.z + xv0.w * a.w
             + xv1.x * b.x + xv1.y * b.y + xv1.z * b.z + xv1.w * b.w;
    }
#pragma unroll
    for (int off = 16; off; off >>= 1)
#pragma unroll
        for (int c = 0; c < 8; c++) d[c] += __shfl_xor_sync(0xffffffffu, d[c], off);
    float best = CUDART_INF_F; int bi = 0x7fffffff;
#pragma unroll
    for (int c = 0; c < 8; c++) {
        float s = fmaf(-2.f, d[c], g_csq[kc[c]]);
        if (s < best || (s == best && kc[c] < bi)) { best = s; bi = kc[c]; }
    }
    if (lane == 0) out[row] = (float)bi;
    const float4* cw = (const float4*)(cb + (size_t)bi * DIM);
    float4* oq = (float4*)(out + NROWS + (size_t)row * DIM);
    oq[lane] = cw[lane];
    oq[lane + 32] = cw[lane + 32];
}

// ---------------------------------------------------------------------------
extern "C" void kernel_launch(void* const* d_in, const int* in_sizes, int n_in,
                              void* d_out, int out_size) {
    const float* x  = (const float*)d_in[0];   // [8, 4096, 256] f32
    const float* cb = (const float*)d_in[1];   // [8192, 256] f32
    float* out = (float*)d_out;

    cudaFuncSetAttribute(vq_main, cudaFuncAttributeMaxDynamicSharedMemorySize,
                         SMEM_TOTAL);

    vq_prep<<<KCODES / 8, 256>>>(cb);
    vq_main<<<NROWS / MT, NTHREADS, SMEM_TOTAL>>>(x);
    vq_rescore<<<NROWS / 8, 256>>>(x, cb, out);
}

// round 15
// speedup vs baseline: 1.0821x; 1.0821x over previous
#include <cuda_runtime.h>
#include <cuda_bf16.h>
#include <cstdint>
#include <math_constants.h>

// ---------------------------------------------------------------------------
// Problem constants
// ---------------------------------------------------------------------------
#define NROWS  32768        // 8 * 4096 query rows
#define KCODES 8192
#define DIM    256          // GEMM-K
#define MT     128          // rows per CTA
#define NTILE  128          // codes per N-tile
#define NTILES (KCODES / NTILE)     // 64

#define NTHREADS 512

// SMEM layout (bytes) -- 105472 total => two CTAs per SM (210944 <= 228KB)
#define ROWA        528     // 256 bf16 + 8 pad (conflict-free ldmatrix)
#define SM_B        67584   // 2 k64-stage buffers after A (128*528)
#define STAGE_BYTES 18432   // 128 codes * 144B
#define ROWB        144     // 128B k64 slice + 16 pad
#define SM_CSQ      104448  // 512B csq tile (+ pad)
#define SMEM_TOTAL  105472

// ---------------------------------------------------------------------------
// Device scratch (no allocations allowed)
// ---------------------------------------------------------------------------
__device__ uint4 g_cb_hi4[KCODES * DIM / 8];   // bf16 hi, 512B per code row
__device__ __align__(16) float g_csq[KCODES];
__device__ int g_cand[NROWS * 8];              // top-2 per warp-column x 4

// ---------------------------------------------------------------------------
// PTX helpers (base ISA only: ldmatrix / mma.sync / cp.async)
// ---------------------------------------------------------------------------
__device__ __forceinline__ uint32_t smem_to_u32(const void* smem_ptr) {
    uint32_t addr;
    asm("{ .reg .u64 tmp; cvta.to.shared.u64 tmp, %1; cvt.u32.u64 %0, tmp; }"
        : "=r"(addr) : "l"(smem_ptr));
    return addr;
}

#define CP_ASYNC16(dst, src) \
    asm volatile("cp.async.cg.shared.global [%0], [%1], 16;" \
        :: "r"((uint32_t)(dst)), "l"((const void*)(src)) : "memory")
#define CP_COMMIT() asm volatile("cp.async.commit_group;" ::: "memory")
#define CP_WAIT(n)  asm volatile("cp.async.wait_group %0;" :: "n"(n) : "memory")

#define LDSM_X4(r, addr) \
    asm volatile("ldmatrix.sync.aligned.m8n8.x4.shared.b16 {%0,%1,%2,%3}, [%4];" \
        : "=r"((r)[0]), "=r"((r)[1]), "=r"((r)[2]), "=r"((r)[3]) : "r"(addr))

#define MMA_BF16(c, a, b) \
    asm volatile("mma.sync.aligned.m16n8k16.row.col.f32.bf16.bf16.f32 " \
        "{%0,%1,%2,%3}, {%4,%5,%6,%7}, {%8,%9}, {%0,%1,%2,%3};" \
        : "+f"((c)[0]), "+f"((c)[1]), "+f"((c)[2]), "+f"((c)[3]) \
        : "r"((a)[0]), "r"((a)[1]), "r"((a)[2]), "r"((a)[3]), \
          "r"((b)[0]), "r"((b)[1]))

// merge candidate (C1,J1) then (C2,J2) into running top-2 (B1,I1,B2,I2)
#define MERGE2(B1, I1, B2, I2, C1, J1, C2, J2) do { \
    if ((C1) < (B1)) { \
        float _nb2; int _ni2; \
        if ((B1) < (C2)) { _nb2 = (B1); _ni2 = (I1); } \
        else             { _nb2 = (C2); _ni2 = (J2); } \
        (B1) = (C1); (I1) = (J1); (B2) = _nb2; (I2) = _ni2; \
    } else if ((C1) < (B2)) { (B2) = (C1); (I2) = (J1); } \
} while (0)

// ---------------------------------------------------------------------------
// Codebook prep: one warp per code row. bf16 hi + fp32 csq.
// ---------------------------------------------------------------------------
__global__ __launch_bounds__(256) void vq_prep(const float* __restrict__ cb) {
    int row  = blockIdx.x * 8 + (threadIdx.x >> 5);
    int lane = threadIdx.x & 31;
    const float4* cr = (const float4*)(cb + (size_t)row * DIM);
    float sq = 0.f;
    uint32_t hw[4];
#pragma unroll
    for (int q = 0; q < 2; q++) {
        float4 v = cr[lane * 2 + q];
        sq += v.x * v.x + v.y * v.y + v.z * v.z + v.w * v.w;
        __nv_bfloat162 p0; p0.x = __float2bfloat16_rn(v.x); p0.y = __float2bfloat16_rn(v.y);
        __nv_bfloat162 p1; p1.x = __float2bfloat16_rn(v.z); p1.y = __float2bfloat16_rn(v.w);
        hw[q * 2 + 0] = *reinterpret_cast<uint32_t*>(&p0);
        hw[q * 2 + 1] = *reinterpret_cast<uint32_t*>(&p1);
    }
    g_cb_hi4[row * 32 + lane] = make_uint4(hw[0], hw[1], hw[2], hw[3]);
#pragma unroll
    for (int off = 16; off; off >>= 1) sq += __shfl_xor_sync(0xffffffffu, sq, off);
    if (lane == 0) g_csq[row] = sq;
}

// ---------------------------------------------------------------------------
// B stage loader: 128 codes x 64 bf16 (one k64 slice) into padded smem rows.
// ---------------------------------------------------------------------------
__device__ __forceinline__ void load_b_stage(uint32_t sbase, int buf, int ktile,
                                             int s, int tid) {
    const char* src = (const char*)g_cb_hi4 + (size_t)ktile * NTILE * 512 + s * 128;
    uint32_t dst = sbase + SM_B + (uint32_t)buf * STAGE_BYTES;
#pragma unroll
    for (int u = tid; u < 1024; u += NTHREADS) {
        int n = u >> 3, j = u & 7;
        CP_ASYNC16(dst + n * ROWB + j * 16, src + (size_t)n * 512 + j * 16);
    }
}

// ---------------------------------------------------------------------------
// Main kernel: grid 256, OCCUPANCY 2, 512 threads / 16 warps of 32x32 tiles
// (4x4 grid). 1-pass bf16, 2-buffer k64 staging. ~256 B LDSM per MMA, 32
// accumulator regs -> no spills under the 128-reg occ-2 cap.
// ---------------------------------------------------------------------------
__global__ __launch_bounds__(NTHREADS, 2) void vq_main(const float* __restrict__ x) {
    extern __shared__ char smem[];
    const uint32_t sbase = smem_to_u32(smem);
    const int tid  = threadIdx.x;
    const int lane = tid & 31;
    const int wm = (tid >> 5) >> 2;          // 0..3 : 32-row band
    const int wn = (tid >> 5) & 3;           // 0..3 : 32-col band
    const int rowBase = blockIdx.x * MT;

    // ---- A -> bf16 in smem (row stride 528B); 512 threads, 4 per row ----
    {
        int r = tid >> 2, h = tid & 3;
        const float4* xr = (const float4*)(x + (size_t)(rowBase + r) * DIM + h * 64);
        uint32_t* ah = (uint32_t*)(smem + r * ROWA + h * 128);
#pragma unroll
        for (int q = 0; q < 16; q++) {
            float4 v = xr[q];
            __nv_bfloat162 p0; p0.x = __float2bfloat16_rn(v.x); p0.y = __float2bfloat16_rn(v.y);
            __nv_bfloat162 p1; p1.x = __float2bfloat16_rn(v.z); p1.y = __float2bfloat16_rn(v.w);
            ah[q * 2 + 0] = *reinterpret_cast<uint32_t*>(&p0);
            ah[q * 2 + 1] = *reinterpret_cast<uint32_t*>(&p1);
        }
    }

    // per-lane ldmatrix base addresses
    const uint32_t aBase = sbase + (uint32_t)((wm * 32 + (lane & 15)) * ROWA
                                              + ((lane >> 4) & 1) * 16);
    // B X4: lanes 0-7 frag(codes c0..c0+7, byte+0), 8-15 (same codes, +16),
    //       16-23 (codes+8, +0), 24-31 (codes+8, +16)
    const uint32_t bLane = (uint32_t)((wn * 32 + ((lane >> 4) & 1) * 8 + (lane & 7)) * ROWB
                                      + ((lane >> 3) & 1) * 16);

    float b1r[4], b2r[4];
    int   i1r[4], i2r[4];
#pragma unroll
    for (int s = 0; s < 4; s++) {
        b1r[s] = CUDART_INF_F; b2r[s] = CUDART_INF_F; i1r[s] = 0; i2r[s] = 1;
    }

    for (int ktile = 0; ktile < NTILES; ktile++) {
        __syncthreads();    // A ready (first iter) / prev epilogue done with csq+B
        load_b_stage(sbase, 0, ktile, 0, tid);
        if (tid < 32) {
            CP_ASYNC16(sbase + SM_CSQ + tid * 16,
                       (const char*)g_csq + (size_t)ktile * 512 + tid * 16);
        }
        CP_COMMIT();

        float c[2][4][4];
#pragma unroll
        for (int a = 0; a < 2; a++)
#pragma unroll
            for (int b = 0; b < 4; b++)
#pragma unroll
                for (int v = 0; v < 4; v++) c[a][b][v] = 0.f;

        for (int s = 0; s < 4; s++) {
            if (s < 3) {
                load_b_stage(sbase, (s + 1) & 1, ktile, s + 1, tid);
                CP_COMMIT();
                CP_WAIT(1);
            } else {
                CP_WAIT(0);
            }
            __syncthreads();
            const uint32_t bufB = sbase + SM_B + ((s & 1) ? STAGE_BYTES : 0);
#pragma unroll
            for (int kk = 0; kk < 4; kk++) {
                uint32_t ah[2][4], bh[2][4];
#pragma unroll
                for (int mt = 0; mt < 2; mt++)
                    LDSM_X4(ah[mt], aBase + mt * (16 * ROWA) + (s * 4 + kk) * 32);
#pragma unroll
                for (int ng = 0; ng < 2; ng++)
                    LDSM_X4(bh[ng], bufB + bLane + ng * (16 * ROWB) + kk * 32);
#pragma unroll
                for (int mt = 0; mt < 2; mt++)
#pragma unroll
                    for (int ng = 0; ng < 2; ng++) {
                        MMA_BF16(c[mt][2 * ng + 0], ah[mt], bh[ng]);
                        MMA_BF16(c[mt][2 * ng + 1], ah[mt], bh[ng] + 2);
                    }
            }
            __syncthreads();   // compute done before next stage overwrites buf
        }

        // ---- epilogue: scores + running top-2 with skip test ----
        const float* csq_s = (const float*)(smem + SM_CSQ);
        float csqr[8];
#pragma unroll
        for (int nt = 0; nt < 4; nt++) {
            csqr[nt * 2 + 0] = csq_s[wn * 32 + nt * 8 + (lane & 3) * 2 + 0];
            csqr[nt * 2 + 1] = csq_s[wn * 32 + nt * 8 + (lane & 3) * 2 + 1];
        }
        const int kb = ktile * NTILE + wn * 32 + (lane & 3) * 2;
#pragma unroll
        for (int slot = 0; slot < 4; slot++) {
            const int mt = slot >> 1, h = slot & 1;
            float m = CUDART_INF_F;
#pragma unroll
            for (int nt = 0; nt < 4; nt++) {
                m = fminf(m, fmaf(-2.f, c[mt][nt][h * 2 + 0], csqr[nt * 2 + 0]));
                m = fminf(m, fmaf(-2.f, c[mt][nt][h * 2 + 1], csqr[nt * 2 + 1]));
            }
            if (m < b2r[slot]) {
#pragma unroll
                for (int nt = 0; nt < 4; nt++)
#pragma unroll
                    for (int u = 0; u < 2; u++) {
                        float sc = fmaf(-2.f, c[mt][nt][h * 2 + u], csqr[nt * 2 + u]);
                        int k = kb + nt * 8 + u;
                        if (sc < b1r[slot]) {
                            b2r[slot] = b1r[slot]; i2r[slot] = i1r[slot];
                            b1r[slot] = sc;        i1r[slot] = k;
                        } else if (sc < b2r[slot]) {
                            b2r[slot] = sc; i2r[slot] = k;
                        }
                    }
            }
        }
    }

    // ---- lane-quad merge (lanes sharing a row differ in lane&3) ----
#pragma unroll
    for (int slot = 0; slot < 4; slot++) {
        float B1 = b1r[slot], B2 = b2r[slot];
        int   I1 = i1r[slot], I2 = i2r[slot];
#pragma unroll
        for (int off = 1; off <= 2; off <<= 1) {
            float C1 = __shfl_xor_sync(0xffffffffu, B1, off);
            int   J1 = __shfl_xor_sync(0xffffffffu, I1, off);
            float C2 = __shfl_xor_sync(0xffffffffu, B2, off);
            int   J2 = __shfl_xor_sync(0xffffffffu, I2, off);
            MERGE2(B1, I1, B2, I2, C1, J1, C2, J2);
        }
        b1r[slot] = B1; i1r[slot] = I1; b2r[slot] = B2; i2r[slot] = I2;
    }

    // ---- write per-warp-column top-2 (8 candidates per row) ----
    __syncthreads();
    int* mi1 = (int*)(smem + SM_B);
    int* mi2 = (int*)(smem + SM_B + 2048);
    if ((lane & 3) == 0) {
#pragma unroll
        for (int slot = 0; slot < 4; slot++) {
            int row = wm * 32 + (slot >> 1) * 16 + (slot & 1) * 8 + (lane >> 2);
            int idx = wn * 128 + row;
            mi1[idx] = i1r[slot]; mi2[idx] = i2r[slot];
        }
    }
    __syncthreads();
    if (tid < 128) {
#pragma unroll
        for (int w = 0; w < 4; w++) {
            g_cand[(rowBase + tid) * 8 + w * 2 + 0] = mi1[w * 128 + tid];
            g_cand[(rowBase + tid) * 8 + w * 2 + 1] = mi2[w * 128 + tid];
        }
    }
}

// ---------------------------------------------------------------------------
// Exact fp32 rescore of 8 candidates + gather. One warp per row.
// ---------------------------------------------------------------------------
__global__ __launch_bounds__(256) void vq_rescore(const float* __restrict__ x,
                                                  const float* __restrict__ cb,
                                                  float* __restrict__ out) {
    int row  = blockIdx.x * 8 + (threadIdx.x >> 5);
    int lane = threadIdx.x & 31;
    int kc[8];
#pragma unroll
    for (int c = 0; c < 8; c++) kc[c] = g_cand[row * 8 + c];
    const float4* xr = (const float4*)(x + (size_t)row * DIM);
    float4 xv0 = xr[lane], xv1 = xr[lane + 32];
    float d[8];
#pragma unroll
    for (int c = 0; c < 8; c++) {
        const float4* cc = (const float4*)(cb + (size_t)kc[c] * DIM);
        float4 a = cc[lane], b = cc[lane + 32];
        d[c] = xv0.x * a.x + xv0.y * a.y + xv0.z * a.z + xv0.w * a.w
             + xv1.x * b.x + xv1.y * b.y + xv1.z * b.z + xv1.w * b.w;
    }
#pragma unroll
    for (int off = 16; off; off >>= 1)
#pragma unroll
        for (int c = 0; c < 8; c++) d[c] += __shfl_xor_sync(0xffffffffu, d[c], off);
    float best = CUDART_INF_F; int bi = 0x7fffffff;
#pragma unroll
    for (int c = 0; c < 8; c++) {
        float s = fmaf(-2.f, d[c], g_csq[kc[c]]);
        if (s < best || (s == best && kc[c] < bi)) { best = s; bi = kc[c]; }
    }
    if (lane == 0) out[row] = (float)bi;
    const float4* cw = (const float4*)(cb + (size_t)bi * DIM);
    float4* oq = (float4*)(out + NROWS + (size_t)row * DIM);
    oq[lane] = cw[lane];
    oq[lane + 32] = cw[lane + 32];
}

// ---------------------------------------------------------------------------
extern "C" void kernel_launch(void* const* d_in, const int* in_sizes, int n_in,
                              void* d_out, int out_size) {
    const float* x  = (const float*)d_in[0];   // [8, 4096, 256] f32
    const float* cb = (const float*)d_in[1];   // [8192, 256] f32
    float* out = (float*)d_out;

    cudaFuncSetAttribute(vq_main, cudaFuncAttributeMaxDynamicSharedMemorySize,
                         SMEM_TOTAL);

    vq_prep<<<KCODES / 8, 256>>>(cb);
    vq_main<<<NROWS / MT, NTHREADS, SMEM_TOTAL>>>(x);
    vq_rescore<<<NROWS / 8, 256>>>(x, cb, out);
}

// round 16
// speedup vs baseline: 1.3143x; 1.2145x over previous
#include <cuda_runtime.h>
#include <cuda_bf16.h>
#include <cstdint>
#include <math_constants.h>

// ---------------------------------------------------------------------------
// Problem constants
// ---------------------------------------------------------------------------
#define NROWS  32768        // 8 * 4096 query rows
#define KCODES 8192
#define DIM    256          // GEMM-K
#define MT     128          // rows per CTA
#define NTILE  128          // codes per N-tile
#define CHUNK  2048         // codes per CTA (4 chunks cover KCODES)
#define NTILES (CHUNK / NTILE)      // 16 ktiles per CTA

#define NTHREADS 256

// SMEM layout (bytes) -- 105472 total => two CTAs per SM (210944 <= 228KB)
#define ROWA        528     // 256 bf16 + 8 pad (conflict-free ldmatrix)
#define SM_B        67584   // 2 k64-stage buffers after A (128*528)
#define STAGE_BYTES 18432   // 128 codes * 144B
#define ROWB        144     // 128B k64 slice + 16 pad
#define SM_CSQ      104448  // 512B csq tile (+ pad)
#define SMEM_TOTAL  105472

// ---------------------------------------------------------------------------
// Device scratch (no allocations allowed)
// ---------------------------------------------------------------------------
__device__ uint4 g_cb_hi4[KCODES * DIM / 8];   // bf16 hi, 512B per code row
__device__ __align__(16) float g_csq[KCODES];
__device__ int g_cand[NROWS * 8];              // 2 per chunk x 4 chunks

// ---------------------------------------------------------------------------
// PTX helpers (base ISA only: ldmatrix / mma.sync / cp.async)
// ---------------------------------------------------------------------------
__device__ __forceinline__ uint32_t smem_to_u32(const void* smem_ptr) {
    uint32_t addr;
    asm("{ .reg .u64 tmp; cvta.to.shared.u64 tmp, %1; cvt.u32.u64 %0, tmp; }"
        : "=r"(addr) : "l"(smem_ptr));
    return addr;
}

#define CP_ASYNC16(dst, src) \
    asm volatile("cp.async.cg.shared.global [%0], [%1], 16;" \
        :: "r"((uint32_t)(dst)), "l"((const void*)(src)) : "memory")
#define CP_COMMIT() asm volatile("cp.async.commit_group;" ::: "memory")
#define CP_WAIT(n)  asm volatile("cp.async.wait_group %0;" :: "n"(n) : "memory")

#define LDSM_X4(r, addr) \
    asm volatile("ldmatrix.sync.aligned.m8n8.x4.shared.b16 {%0,%1,%2,%3}, [%4];" \
        : "=r"((r)[0]), "=r"((r)[1]), "=r"((r)[2]), "=r"((r)[3]) : "r"(addr))

#define MMA_BF16(c, a, b) \
    asm volatile("mma.sync.aligned.m16n8k16.row.col.f32.bf16.bf16.f32 " \
        "{%0,%1,%2,%3}, {%4,%5,%6,%7}, {%8,%9}, {%0,%1,%2,%3};" \
        : "+f"((c)[0]), "+f"((c)[1]), "+f"((c)[2]), "+f"((c)[3]) \
        : "r"((a)[0]), "r"((a)[1]), "r"((a)[2]), "r"((a)[3]), \
          "r"((b)[0]), "r"((b)[1]))

// merge candidate (C1,J1) then (C2,J2) into running top-2 (B1,I1,B2,I2)
#define MERGE2(B1, I1, B2, I2, C1, J1, C2, J2) do { \
    if ((C1) < (B1)) { \
        float _nb2; int _ni2; \
        if ((B1) < (C2)) { _nb2 = (B1); _ni2 = (I1); } \
        else             { _nb2 = (C2); _ni2 = (J2); } \
        (B1) = (C1); (I1) = (J1); (B2) = _nb2; (I2) = _ni2; \
    } else if ((C1) < (B2)) { (B2) = (C1); (I2) = (J1); } \
} while (0)

// ---------------------------------------------------------------------------
// Codebook prep: one warp per code row. bf16 hi + fp32 csq.
// ---------------------------------------------------------------------------
__global__ __launch_bounds__(256) void vq_prep(const float* __restrict__ cb) {
    int row  = blockIdx.x * 8 + (threadIdx.x >> 5);
    int lane = threadIdx.x & 31;
    const float4* cr = (const float4*)(cb + (size_t)row * DIM);
    float sq = 0.f;
    uint32_t hw[4];
#pragma unroll
    for (int q = 0; q < 2; q++) {
        float4 v = cr[lane * 2 + q];
        sq += v.x * v.x + v.y * v.y + v.z * v.z + v.w * v.w;
        __nv_bfloat162 p0; p0.x = __float2bfloat16_rn(v.x); p0.y = __float2bfloat16_rn(v.y);
        __nv_bfloat162 p1; p1.x = __float2bfloat16_rn(v.z); p1.y = __float2bfloat16_rn(v.w);
        hw[q * 2 + 0] = *reinterpret_cast<uint32_t*>(&p0);
        hw[q * 2 + 1] = *reinterpret_cast<uint32_t*>(&p1);
    }
    g_cb_hi4[row * 32 + lane] = make_uint4(hw[0], hw[1], hw[2], hw[3]);
#pragma unroll
    for (int off = 16; off; off >>= 1) sq += __shfl_xor_sync(0xffffffffu, sq, off);
    if (lane == 0) g_csq[row] = sq;
}

// ---------------------------------------------------------------------------
// B stage loader: 128 codes x 64 bf16 (one k64 slice) into padded smem rows.
// ---------------------------------------------------------------------------
__device__ __forceinline__ void load_b_stage(uint32_t sbase, int buf, int ktileG,
                                             int s, int tid) {
    const char* src = (const char*)g_cb_hi4 + (size_t)ktileG * NTILE * 512 + s * 128;
    uint32_t dst = sbase + SM_B + (uint32_t)buf * STAGE_BYTES;
#pragma unroll
    for (int u = tid; u < 1024; u += NTHREADS) {
        int n = u >> 3, j = u & 7;
        CP_ASYNC16(dst + n * ROWB + j * 16, src + (size_t)n * 512 + j * 16);
    }
}

// ---------------------------------------------------------------------------
// Main kernel: grid 1024 (256 row-blocks x 4 code chunks), OCCUPANCY 2.
// 8 warps of 32x64 tiles (2.67 MMA per LDSM, 192 B/MMA), 1-pass bf16,
// 2-buffer k64 staging, per-row chunk top-2 -> g_cand.
// ---------------------------------------------------------------------------
__global__ __launch_bounds__(NTHREADS, 2) void vq_main(const float* __restrict__ x) {
    extern __shared__ char smem[];
    const uint32_t sbase = smem_to_u32(smem);
    const int tid  = threadIdx.x;
    const int lane = tid & 31;
    const int wm = (tid >> 5) >> 1;          // 0..3 : 32-row band
    const int wn = (tid >> 5) & 1;           // 0..1 : 64-col band
    const int rowBase   = (blockIdx.x >> 2) * MT;
    const int chunk     = blockIdx.x & 3;
    const int ktileBase = chunk * NTILES;    // global ktile offset

    // ---- A -> bf16 in smem (row stride 528B) ----
    {
        int r = tid >> 1, h = tid & 1;
        const float4* xr = (const float4*)(x + (size_t)(rowBase + r) * DIM + h * 128);
        uint32_t* ah = (uint32_t*)(smem + r * ROWA + h * 256);
#pragma unroll
        for (int q = 0; q < 32; q++) {
            float4 v = xr[q];
            __nv_bfloat162 p0; p0.x = __float2bfloat16_rn(v.x); p0.y = __float2bfloat16_rn(v.y);
            __nv_bfloat162 p1; p1.x = __float2bfloat16_rn(v.z); p1.y = __float2bfloat16_rn(v.w);
            ah[q * 2 + 0] = *reinterpret_cast<uint32_t*>(&p0);
            ah[q * 2 + 1] = *reinterpret_cast<uint32_t*>(&p1);
        }
    }

    // per-lane ldmatrix base addresses
    const uint32_t aBase = sbase + (uint32_t)((wm * 32 + (lane & 15)) * ROWA
                                              + ((lane >> 4) & 1) * 16);
    const uint32_t bLane = (uint32_t)((wn * 64 + ((lane >> 4) & 1) * 8 + (lane & 7)) * ROWB
                                      + ((lane >> 3) & 1) * 16);

    float b1r[4], b2r[4];
    int   i1r[4], i2r[4];
#pragma unroll
    for (int s = 0; s < 4; s++) {
        b1r[s] = CUDART_INF_F; b2r[s] = CUDART_INF_F; i1r[s] = 0; i2r[s] = 1;
    }

    for (int kt = 0; kt < NTILES; kt++) {
        const int ktileG = ktileBase + kt;
        __syncthreads();    // A ready (first iter) / prev epilogue done with csq+B
        load_b_stage(sbase, 0, ktileG, 0, tid);
        if (tid < 32) {
            CP_ASYNC16(sbase + SM_CSQ + tid * 16,
                       (const char*)g_csq + (size_t)ktileG * 512 + tid * 16);
        }
        CP_COMMIT();

        float c[2][8][4];
#pragma unroll
        for (int a = 0; a < 2; a++)
#pragma unroll
            for (int b = 0; b < 8; b++)
#pragma unroll
                for (int v = 0; v < 4; v++) c[a][b][v] = 0.f;

        for (int s = 0; s < 4; s++) {
            if (s < 3) {
                load_b_stage(sbase, (s + 1) & 1, ktileG, s + 1, tid);
                CP_COMMIT();
                CP_WAIT(1);
            } else {
                CP_WAIT(0);
            }
            __syncthreads();
            const uint32_t bufB = sbase + SM_B + ((s & 1) ? STAGE_BYTES : 0);
#pragma unroll
            for (int kk = 0; kk < 4; kk++) {
                uint32_t ah[2][4], bh[4][4];
#pragma unroll
                for (int mt = 0; mt < 2; mt++)
                    LDSM_X4(ah[mt], aBase + mt * (16 * ROWA) + (s * 4 + kk) * 32);
#pragma unroll
                for (int ng = 0; ng < 4; ng++)
                    LDSM_X4(bh[ng], bufB + bLane + ng * (16 * ROWB) + kk * 32);
#pragma unroll
                for (int mt = 0; mt < 2; mt++)
#pragma unroll
                    for (int ng = 0; ng < 4; ng++) {
                        MMA_BF16(c[mt][2 * ng + 0], ah[mt], bh[ng]);
                        MMA_BF16(c[mt][2 * ng + 1], ah[mt], bh[ng] + 2);
                    }
            }
            __syncthreads();   // compute done before next stage overwrites buf
        }

        // ---- epilogue: scores + running top-2 with skip test ----
        const float* csq_s = (const float*)(smem + SM_CSQ) + wn * 64 + (lane & 3) * 2;
        const int kb = ktileG * NTILE + wn * 64 + (lane & 3) * 2;
#pragma unroll
        for (int slot = 0; slot < 4; slot++) {
            const int mt = slot >> 1, h = slot & 1;
            float m = CUDART_INF_F;
#pragma unroll
            for (int nt = 0; nt < 8; nt++) {
                m = fminf(m, fmaf(-2.f, c[mt][nt][h * 2 + 0], csq_s[nt * 8 + 0]));
                m = fminf(m, fmaf(-2.f, c[mt][nt][h * 2 + 1], csq_s[nt * 8 + 1]));
            }
            if (m < b2r[slot]) {
#pragma unroll
                for (int nt = 0; nt < 8; nt++)
#pragma unroll
                    for (int u = 0; u < 2; u++) {
                        float sc = fmaf(-2.f, c[mt][nt][h * 2 + u], csq_s[nt * 8 + u]);
                        int k = kb + nt * 8 + u;
                        if (sc < b1r[slot]) {
                            b2r[slot] = b1r[slot]; i2r[slot] = i1r[slot];
                            b1r[slot] = sc;        i1r[slot] = k;
                        } else if (sc < b2r[slot]) {
                            b2r[slot] = sc; i2r[slot] = k;
                        }
                    }
            }
        }
    }

    // ---- lane-quad merge (lanes sharing a row differ in lane&3) ----
#pragma unroll
    for (int slot = 0; slot < 4; slot++) {
        float B1 = b1r[slot], B2 = b2r[slot];
        int   I1 = i1r[slot], I2 = i2r[slot];
#pragma unroll
        for (int off = 1; off <= 2; off <<= 1) {
            float C1 = __shfl_xor_sync(0xffffffffu, B1, off);
            int   J1 = __shfl_xor_sync(0xffffffffu, I1, off);
            float C2 = __shfl_xor_sync(0xffffffffu, B2, off);
            int   J2 = __shfl_xor_sync(0xffffffffu, I2, off);
            MERGE2(B1, I1, B2, I2, C1, J1, C2, J2);
        }
        b1r[slot] = B1; i1r[slot] = I1; b2r[slot] = B2; i2r[slot] = I2;
    }

    // ---- cross-warp-column merge -> top-2 per row for this chunk ----
    __syncthreads();
    float* mb1 = (float*)(smem + SM_B);
    int*   mi1 = (int*)  (smem + SM_B + 1024);
    float* mb2 = (float*)(smem + SM_B + 2048);
    int*   mi2 = (int*)  (smem + SM_B + 3072);
    if ((lane & 3) == 0) {
#pragma unroll
        for (int slot = 0; slot < 4; slot++) {
            int row = wm * 32 + (slot >> 1) * 16 + (slot & 1) * 8 + (lane >> 2);
            int idx = wn * 128 + row;
            mb1[idx] = b1r[slot]; mi1[idx] = i1r[slot];
            mb2[idx] = b2r[slot]; mi2[idx] = i2r[slot];
        }
    }
    __syncthreads();
    if (tid < 128) {
        float B1 = mb1[tid], B2 = mb2[tid];
        int   I1 = mi1[tid], I2 = mi2[tid];
        float C1 = mb1[128 + tid]; int J1 = mi1[128 + tid];
        float C2 = mb2[128 + tid]; int J2 = mi2[128 + tid];
        MERGE2(B1, I1, B2, I2, C1, J1, C2, J2);
        g_cand[(rowBase + tid) * 8 + chunk * 2 + 0] = I1;
        g_cand[(rowBase + tid) * 8 + chunk * 2 + 1] = I2;
    }
}

// ---------------------------------------------------------------------------
// Exact fp32 rescore of 8 candidates + gather. One warp per row.
// ---------------------------------------------------------------------------
__global__ __launch_bounds__(256) void vq_rescore(const float* __restrict__ x,
                                                  const float* __restrict__ cb,
                                                  float* __restrict__ out) {
    int row  = blockIdx.x * 8 + (threadIdx.x >> 5);
    int lane = threadIdx.x & 31;
    int kc[8];
#pragma unroll
    for (int c = 0; c < 8; c++) kc[c] = g_cand[row * 8 + c];
    const float4* xr = (const float4*)(x + (size_t)row * DIM);
    float4 xv0 = xr[lane], xv1 = xr[lane + 32];
    float d[8];
#pragma unroll
    for (int c = 0; c < 8; c++) {
        const float4* cc = (const float4*)(cb + (size_t)kc[c] * DIM);
        float4 a = cc[lane], b = cc[lane + 32];
        d[c] = xv0.x * a.x + xv0.y * a.y + xv0.z * a.z + xv0.w * a.w
             + xv1.x * b.x + xv1.y * b.y + xv1.z * b.z + xv1.w * b.w;
    }
#pragma unroll
    for (int off = 16; off; off >>= 1)
#pragma unroll
        for (int c = 0; c < 8; c++) d[c] += __shfl_xor_sync(0xffffffffu, d[c], off);
    float best = CUDART_INF_F; int bi = 0x7fffffff;
#pragma unroll
    for (int c = 0; c < 8; c++) {
        float s = fmaf(-2.f, d[c], g_csq[kc[c]]);
        if (s < best || (s == best && kc[c] < bi)) { best = s; bi = kc[c]; }
    }
    if (lane == 0) out[row] = (float)bi;
    const float4* cw = (const float4*)(cb + (size_t)bi * DIM);
    float4* oq = (float4*)(out + NROWS + (size_t)row * DIM);
    oq[lane] = cw[lane];
    oq[lane + 32] = cw[lane + 32];
}

// ---------------------------------------------------------------------------
extern "C" void kernel_launch(void* const* d_in, const int* in_sizes, int n_in,
                              void* d_out, int out_size) {
    const float* x  = (const float*)d_in[0];   // [8, 4096, 256] f32
    const float* cb = (const float*)d_in[1];   // [8192, 256] f32
    float* out = (float*)d_out;

    cudaFuncSetAttribute(vq_main, cudaFuncAttributeMaxDynamicSharedMemorySize,
                         SMEM_TOTAL);

    vq_prep<<<KCODES / 8, 256>>>(cb);
    vq_main<<<(NROWS / MT) * 4, NTHREADS, SMEM_TOTAL>>>(x);
    vq_rescore<<<NROWS / 8, 256>>>(x, cb, out);
}

// round 17
// speedup vs baseline: 1.3791x; 1.0493x over previous
#include <cuda_runtime.h>
#include <cuda_bf16.h>
#include <cstdint>
#include <math_constants.h>

// ---------------------------------------------------------------------------
// Problem constants
// ---------------------------------------------------------------------------
#define NROWS  32768        // 8 * 4096 query rows
#define KCODES 8192
#define DIM    256          // GEMM-K
#define MT     128          // rows per CTA
#define NTILE  128          // codes per N-tile
#define NCHUNK 8            // code chunks (1024 codes each)
#define NTILES 8            // ktiles per CTA (chunk / NTILE)

#define NTHREADS 256

// SMEM layout (bytes) -- 105472 total => two CTAs per SM (210944 <= 228KB)
#define ROWA        528     // 256 bf16 + 8 pad (conflict-free ldmatrix)
#define SM_B        67584   // 2 k64-stage buffers after A (128*528)
#define STAGE_BYTES 18432   // 128 codes * 144B
#define ROWB        144     // 128B k64 slice + 16 pad
#define SM_CSQ      104448  // 512B csq tile (+ pad)
#define SMEM_TOTAL  105472

// ---------------------------------------------------------------------------
// Device scratch (no allocations allowed)
// ---------------------------------------------------------------------------
__device__ uint4 g_cb_hi4[KCODES * DIM / 8];   // bf16 codebook, 512B per row
__device__ uint4 g_x_hi4[NROWS * DIM / 8];     // bf16 queries, 512B per row
__device__ __align__(16) float g_csq[KCODES];
__device__ int g_cand[NROWS * 16];             // 2 per chunk x 8 chunks

// ---------------------------------------------------------------------------
// PTX helpers (base ISA only: ldmatrix / mma.sync / cp.async)
// ---------------------------------------------------------------------------
__device__ __forceinline__ uint32_t smem_to_u32(const void* smem_ptr) {
    uint32_t addr;
    asm("{ .reg .u64 tmp; cvta.to.shared.u64 tmp, %1; cvt.u32.u64 %0, tmp; }"
        : "=r"(addr) : "l"(smem_ptr));
    return addr;
}

#define CP_ASYNC16(dst, src) \
    asm volatile("cp.async.cg.shared.global [%0], [%1], 16;" \
        :: "r"((uint32_t)(dst)), "l"((const void*)(src)) : "memory")
#define CP_COMMIT() asm volatile("cp.async.commit_group;" ::: "memory")
#define CP_WAIT(n)  asm volatile("cp.async.wait_group %0;" :: "n"(n) : "memory")

#define LDSM_X4(r, addr) \
    asm volatile("ldmatrix.sync.aligned.m8n8.x4.shared.b16 {%0,%1,%2,%3}, [%4];" \
        : "=r"((r)[0]), "=r"((r)[1]), "=r"((r)[2]), "=r"((r)[3]) : "r"(addr))

#define MMA_BF16(c, a, b) \
    asm volatile("mma.sync.aligned.m16n8k16.row.col.f32.bf16.bf16.f32 " \
        "{%0,%1,%2,%3}, {%4,%5,%6,%7}, {%8,%9}, {%0,%1,%2,%3};" \
        : "+f"((c)[0]), "+f"((c)[1]), "+f"((c)[2]), "+f"((c)[3]) \
        : "r"((a)[0]), "r"((a)[1]), "r"((a)[2]), "r"((a)[3]), \
          "r"((b)[0]), "r"((b)[1]))

// merge candidate (C1,J1) then (C2,J2) into running top-2 (B1,I1,B2,I2)
#define MERGE2(B1, I1, B2, I2, C1, J1, C2, J2) do { \
    if ((C1) < (B1)) { \
        float _nb2; int _ni2; \
        if ((B1) < (C2)) { _nb2 = (B1); _ni2 = (I1); } \
        else             { _nb2 = (C2); _ni2 = (J2); } \
        (B1) = (C1); (I1) = (J1); (B2) = _nb2; (I2) = _ni2; \
    } else if ((C1) < (B2)) { (B2) = (C1); (I2) = (J1); } \
} while (0)

// ---------------------------------------------------------------------------
// Codebook prep: one warp per code row. bf16 + fp32 csq.
// ---------------------------------------------------------------------------
__global__ __launch_bounds__(256) void vq_prep(const float* __restrict__ cb) {
    int row  = blockIdx.x * 8 + (threadIdx.x >> 5);
    int lane = threadIdx.x & 31;
    const float4* cr = (const float4*)(cb + (size_t)row * DIM);
    float sq = 0.f;
    uint32_t hw[4];
#pragma unroll
    for (int q = 0; q < 2; q++) {
        float4 v = cr[lane * 2 + q];
        sq += v.x * v.x + v.y * v.y + v.z * v.z + v.w * v.w;
        __nv_bfloat162 p0; p0.x = __float2bfloat16_rn(v.x); p0.y = __float2bfloat16_rn(v.y);
        __nv_bfloat162 p1; p1.x = __float2bfloat16_rn(v.z); p1.y = __float2bfloat16_rn(v.w);
        hw[q * 2 + 0] = *reinterpret_cast<uint32_t*>(&p0);
        hw[q * 2 + 1] = *reinterpret_cast<uint32_t*>(&p1);
    }
    g_cb_hi4[row * 32 + lane] = make_uint4(hw[0], hw[1], hw[2], hw[3]);
#pragma unroll
    for (int off = 16; off; off >>= 1) sq += __shfl_xor_sync(0xffffffffu, sq, off);
    if (lane == 0) g_csq[row] = sq;
}

// ---------------------------------------------------------------------------
// Query prep: one warp per x row -> bf16 (no norms needed).
// ---------------------------------------------------------------------------
__global__ __launch_bounds__(256) void vq_prep_x(const float* __restrict__ x) {
    int row  = blockIdx.x * 8 + (threadIdx.x >> 5);
    int lane = threadIdx.x & 31;
    const float4* xr = (const float4*)(x + (size_t)row * DIM);
    uint32_t hw[4];
#pragma unroll
    for (int q = 0; q < 2; q++) {
        float4 v = xr[lane * 2 + q];
        __nv_bfloat162 p0; p0.x = __float2bfloat16_rn(v.x); p0.y = __float2bfloat16_rn(v.y);
        __nv_bfloat162 p1; p1.x = __float2bfloat16_rn(v.z); p1.y = __float2bfloat16_rn(v.w);
        hw[q * 2 + 0] = *reinterpret_cast<uint32_t*>(&p0);
        hw[q * 2 + 1] = *reinterpret_cast<uint32_t*>(&p1);
    }
    g_x_hi4[row * 32 + lane] = make_uint4(hw[0], hw[1], hw[2], hw[3]);
}

// ---------------------------------------------------------------------------
// B stage loader: 128 codes x 64 bf16 (one k64 slice) into padded smem rows.
// ---------------------------------------------------------------------------
__device__ __forceinline__ void load_b_stage(uint32_t sbase, int buf, int ktileG,
                                             int s, int tid) {
    const char* src = (const char*)g_cb_hi4 + (size_t)ktileG * NTILE * 512 + s * 128;
    uint32_t dst = sbase + SM_B + (uint32_t)buf * STAGE_BYTES;
#pragma unroll
    for (int u = tid; u < 1024; u += NTHREADS) {
        int n = u >> 3, j = u & 7;
        CP_ASYNC16(dst + n * ROWB + j * 16, src + (size_t)n * 512 + j * 16);
    }
}

// ---------------------------------------------------------------------------
// Main kernel: grid 2048 (256 row-blocks x 8 chunks of 1024 codes), OCC 2.
// 8 warps of 32x64 tiles, 1-pass bf16, 2-buffer k64 staging. A tile comes
// straight from pre-converted g_x_hi4 via cp.async (no per-CTA conversion).
// ---------------------------------------------------------------------------
__global__ __launch_bounds__(NTHREADS, 2) void vq_main() {
    extern __shared__ char smem[];
    const uint32_t sbase = smem_to_u32(smem);
    const int tid  = threadIdx.x;
    const int lane = tid & 31;
    const int wm = (tid >> 5) >> 1;          // 0..3 : 32-row band
    const int wn = (tid >> 5) & 1;           // 0..1 : 64-col band
    const int rowBase   = (int)(blockIdx.x >> 3) * MT;
    const int chunk     = blockIdx.x & 7;
    const int ktileBase = chunk * NTILES;    // global ktile offset

    // ---- A tile: cp.async 128 rows x 512B from g_x_hi4 (row stride 528) ----
    {
        const char* srcA = (const char*)g_x_hi4 + (size_t)rowBase * 512;
#pragma unroll
        for (int u = tid; u < 4096; u += NTHREADS) {
            int r = u >> 5, j = u & 31;
            CP_ASYNC16(sbase + r * ROWA + j * 16, srcA + (size_t)r * 512 + j * 16);
        }
        CP_COMMIT();
    }

    // per-lane ldmatrix base addresses
    const uint32_t aBase = sbase + (uint32_t)((wm * 32 + (lane & 15)) * ROWA
                                              + ((lane >> 4) & 1) * 16);
    const uint32_t bLane = (uint32_t)((wn * 64 + ((lane >> 4) & 1) * 8 + (lane & 7)) * ROWB
                                      + ((lane >> 3) & 1) * 16);

    float b1r[4], b2r[4];
    int   i1r[4], i2r[4];
#pragma unroll
    for (int s = 0; s < 4; s++) {
        b1r[s] = CUDART_INF_F; b2r[s] = CUDART_INF_F; i1r[s] = 0; i2r[s] = 1;
    }

    for (int kt = 0; kt < NTILES; kt++) {
        const int ktileG = ktileBase + kt;
        __syncthreads();    // prev epilogue done with csq+B (no-op cost first iter)
        load_b_stage(sbase, 0, ktileG, 0, tid);
        if (tid < 32) {
            CP_ASYNC16(sbase + SM_CSQ + tid * 16,
                       (const char*)g_csq + (size_t)ktileG * 512 + tid * 16);
        }
        CP_COMMIT();

        float c[2][8][4];
#pragma unroll
        for (int a = 0; a < 2; a++)
#pragma unroll
            for (int b = 0; b < 8; b++)
#pragma unroll
                for (int v = 0; v < 4; v++) c[a][b][v] = 0.f;

        for (int s = 0; s < 4; s++) {
            if (s < 3) {
                load_b_stage(sbase, (s + 1) & 1, ktileG, s + 1, tid);
                CP_COMMIT();
                CP_WAIT(1);
            } else {
                CP_WAIT(0);
            }
            __syncthreads();
            const uint32_t bufB = sbase + SM_B + ((s & 1) ? STAGE_BYTES : 0);
#pragma unroll
            for (int kk = 0; kk < 4; kk++) {
                uint32_t ah[2][4], bh[4][4];
#pragma unroll
                for (int mt = 0; mt < 2; mt++)
                    LDSM_X4(ah[mt], aBase + mt * (16 * ROWA) + (s * 4 + kk) * 32);
#pragma unroll
                for (int ng = 0; ng < 4; ng++)
                    LDSM_X4(bh[ng], bufB + bLane + ng * (16 * ROWB) + kk * 32);
#pragma unroll
                for (int mt = 0; mt < 2; mt++)
#pragma unroll
                    for (int ng = 0; ng < 4; ng++) {
                        MMA_BF16(c[mt][2 * ng + 0], ah[mt], bh[ng]);
                        MMA_BF16(c[mt][2 * ng + 1], ah[mt], bh[ng] + 2);
                    }
            }
            __syncthreads();   // compute done before next stage overwrites buf
        }

        // ---- epilogue: scores + running top-2 with skip test ----
        const float* csq_s = (const float*)(smem + SM_CSQ) + wn * 64 + (lane & 3) * 2;
        const int kb = ktileG * NTILE + wn * 64 + (lane & 3) * 2;
#pragma unroll
        for (int slot = 0; slot < 4; slot++) {
            const int mt = slot >> 1, h = slot & 1;
            float m = CUDART_INF_F;
#pragma unroll
            for (int nt = 0; nt < 8; nt++) {
                m = fminf(m, fmaf(-2.f, c[mt][nt][h * 2 + 0], csq_s[nt * 8 + 0]));
                m = fminf(m, fmaf(-2.f, c[mt][nt][h * 2 + 1], csq_s[nt * 8 + 1]));
            }
            if (m < b2r[slot]) {
#pragma unroll
                for (int nt = 0; nt < 8; nt++)
#pragma unroll
                    for (int u = 0; u < 2; u++) {
                        float sc = fmaf(-2.f, c[mt][nt][h * 2 + u], csq_s[nt * 8 + u]);
                        int k = kb + nt * 8 + u;
                        if (sc < b1r[slot]) {
                            b2r[slot] = b1r[slot]; i2r[slot] = i1r[slot];
                            b1r[slot] = sc;        i1r[slot] = k;
                        } else if (sc < b2r[slot]) {
                            b2r[slot] = sc; i2r[slot] = k;
                        }
                    }
            }
        }
    }

    // ---- lane-quad merge (lanes sharing a row differ in lane&3) ----
#pragma unroll
    for (int slot = 0; slot < 4; slot++) {
        float B1 = b1r[slot], B2 = b2r[slot];
        int   I1 = i1r[slot], I2 = i2r[slot];
#pragma unroll
        for (int off = 1; off <= 2; off <<= 1) {
            float C1 = __shfl_xor_sync(0xffffffffu, B1, off);
            int   J1 = __shfl_xor_sync(0xffffffffu, I1, off);
            float C2 = __shfl_xor_sync(0xffffffffu, B2, off);
            int   J2 = __shfl_xor_sync(0xffffffffu, I2, off);
            MERGE2(B1, I1, B2, I2, C1, J1, C2, J2);
        }
        b1r[slot] = B1; i1r[slot] = I1; b2r[slot] = B2; i2r[slot] = I2;
    }

    // ---- cross-warp-column merge -> top-2 per row for this chunk ----
    __syncthreads();
    float* mb1 = (float*)(smem + SM_B);
    int*   mi1 = (int*)  (smem + SM_B + 1024);
    float* mb2 = (float*)(smem + SM_B + 2048);
    int*   mi2 = (int*)  (smem + SM_B + 3072);
    if ((lane & 3) == 0) {
#pragma unroll
        for (int slot = 0; slot < 4; slot++) {
            int row = wm * 32 + (slot >> 1) * 16 + (slot & 1) * 8 + (lane >> 2);
            int idx = wn * 128 + row;
            mb1[idx] = b1r[slot]; mi1[idx] = i1r[slot];
            mb2[idx] = b2r[slot]; mi2[idx] = i2r[slot];
        }
    }
    __syncthreads();
    if (tid < 128) {
        float B1 = mb1[tid], B2 = mb2[tid];
        int   I1 = mi1[tid], I2 = mi2[tid];
        float C1 = mb1[128 + tid]; int J1 = mi1[128 + tid];
        float C2 = mb2[128 + tid]; int J2 = mi2[128 + tid];
        MERGE2(B1, I1, B2, I2, C1, J1, C2, J2);
        g_cand[(rowBase + tid) * 16 + chunk * 2 + 0] = I1;
        g_cand[(rowBase + tid) * 16 + chunk * 2 + 1] = I2;
    }
}

// ---------------------------------------------------------------------------
// Exact fp32 rescore of 16 candidates + gather. One warp per row.
// ---------------------------------------------------------------------------
__global__ __launch_bounds__(256) void vq_rescore(const float* __restrict__ x,
                                                  const float* __restrict__ cb,
                                                  float* __restrict__ out) {
    int row  = blockIdx.x * 8 + (threadIdx.x >> 5);
    int lane = threadIdx.x & 31;
    const float4* xr = (const float4*)(x + (size_t)row * DIM);
    float4 xv0 = xr[lane], xv1 = xr[lane + 32];

    float best = CUDART_INF_F; int bi = 0x7fffffff;
#pragma unroll
    for (int g = 0; g < 2; g++) {
        int kc[8];
        float d[8];
#pragma unroll
        for (int c = 0; c < 8; c++) {
            kc[c] = g_cand[row * 16 + g * 8 + c];
            const float4* cc = (const float4*)(cb + (size_t)kc[c] * DIM);
            float4 a = cc[lane], b = cc[lane + 32];
            d[c] = xv0.x * a.x + xv0.y * a.y + xv0.z * a.z + xv0.w * a.w
                 + xv1.x * b.x + xv1.y * b.y + xv1.z * b.z + xv1.w * b.w;
        }
#pragma unroll
        for (int off = 16; off; off >>= 1)
#pragma unroll
            for (int c = 0; c < 8; c++) d[c] += __shfl_xor_sync(0xffffffffu, d[c], off);
#pragma unroll
        for (int c = 0; c < 8; c++) {
            float s = fmaf(-2.f, d[c], g_csq[kc[c]]);
            if (s < best || (s == best && kc[c] < bi)) { best = s; bi = kc[c]; }
        }
    }
    if (lane == 0) out[row] = (float)bi;
    const float4* cw = (const float4*)(cb + (size_t)bi * DIM);
    float4* oq = (float4*)(out + NROWS + (size_t)row * DIM);
    oq[lane] = cw[lane];
    oq[lane + 32] = cw[lane + 32];
}

// ---------------------------------------------------------------------------
extern "C" void kernel_launch(void* const* d_in, const int* in_sizes, int n_in,
                              void* d_out, int out_size) {
    const float* x  = (const float*)d_in[0];   // [8, 4096, 256] f32
    const float* cb = (const float*)d_in[1];   // [8192, 256] f32
    float* out = (float*)d_out;

    cudaFuncSetAttribute(vq_main, cudaFuncAttributeMaxDynamicSharedMemorySize,
                         SMEM_TOTAL);

    vq_prep<<<KCODES / 8, 256>>>(cb);
    vq_prep_x<<<NROWS / 8, 256>>>(x);
    vq_main<<<(NROWS / MT) * NCHUNK, NTHREADS, SMEM_TOTAL>>>();
    vq_rescore<<<NROWS / 8, 256>>>(x, cb, out);
}